// round 2
// baseline (speedup 1.0000x reference)
#include <cuda_runtime.h>
#include <cstdint>
#include <cstddef>

#define NPTS   4096
#define MANCH  128
#define GC0    64
#define GC1    128
#define KNN    32
#define RR2    0.0225f
#define GTOT   64
#define FPS_THREADS 512
#define CONV_THREADS 256

// Exact (non-FMA-contracted) squared distance, matching the reference's
// mul,mul,mul,add,add evaluation so discrete decisions (argmax / radius
// threshold) agree bit-for-bit with the JAX reference.
__device__ __forceinline__ float dist2_precise(float ax, float ay, float az,
                                               float bx, float by, float bz) {
    float dx = __fsub_rn(ax, bx);
    float dy = __fsub_rn(ay, by);
    float dz = __fsub_rn(az, bz);
    return __fadd_rn(__fadd_rn(__fmul_rn(dx, dx), __fmul_rn(dy, dy)),
                     __fmul_rn(dz, dz));
}

// ---------------------------------------------------------------------------
// Kernel A: furthest point sampling. One block per group (64 blocks).
// Writes anchor coords straight into d_out's new_xyzs region: out[(g*128+m)*3+c]
// ---------------------------------------------------------------------------
__global__ void fps_kernel(const float* __restrict__ xyzs, float* __restrict__ out) {
    extern __shared__ float sm[];
    float* sx = sm;
    float* sy = sm + NPTS;
    float* sz = sm + 2 * NPTS;
    __shared__ float redV[16];
    __shared__ int   redI[16];
    __shared__ float curP[3];

    int g = blockIdx.x;
    int b = g >> 4, f = g & 15;
    int t = 2 * f;  // center frame index into xyzs (0..30, never clamped)
    const float* frame = xyzs + ((size_t)(b * 32 + t)) * NPTS * 3;
    int tid = threadIdx.x;

    for (int i = tid; i < NPTS; i += FPS_THREADS) {
        sx[i] = frame[3 * i + 0];
        sy[i] = frame[3 * i + 1];
        sz[i] = frame[3 * i + 2];
    }
    __syncthreads();

    if (tid == 0) {
        float* ap = out + (size_t)g * MANCH * 3;
        ap[0] = sx[0]; ap[1] = sy[0]; ap[2] = sz[0];
    }

    float dist[8];
#pragma unroll
    for (int s = 0; s < 8; s++) dist[s] = 1e10f;

    float px = sx[0], py = sy[0], pz = sz[0];

    for (int step = 1; step < MANCH; step++) {
        float bv = -1.0f;
        int   bi = NPTS;
#pragma unroll
        for (int s = 0; s < 8; s++) {
            int i = tid + s * FPS_THREADS;
            float d2 = dist2_precise(sx[i], sy[i], sz[i], px, py, pz);
            float dd = fminf(dist[s], d2);
            dist[s] = dd;
            if (dd > bv || (dd == bv && i < bi)) { bv = dd; bi = i; }
        }
        // warp argmax (first-occurrence tie-break: larger val, or equal & smaller idx)
#pragma unroll
        for (int off = 16; off; off >>= 1) {
            float ov = __shfl_down_sync(0xffffffffu, bv, off);
            int   oi = __shfl_down_sync(0xffffffffu, bi, off);
            if (ov > bv || (ov == bv && oi < bi)) { bv = ov; bi = oi; }
        }
        if ((tid & 31) == 0) { redV[tid >> 5] = bv; redI[tid >> 5] = bi; }
        __syncthreads();
        if (tid < 32) {
            bv = (tid < 16) ? redV[tid] : -1.0f;
            bi = (tid < 16) ? redI[tid] : NPTS;
#pragma unroll
            for (int off = 8; off; off >>= 1) {
                float ov = __shfl_down_sync(0xffffffffu, bv, off);
                int   oi = __shfl_down_sync(0xffffffffu, bi, off);
                if (ov > bv || (ov == bv && oi < bi)) { bv = ov; bi = oi; }
            }
            if (tid == 0) {
                curP[0] = sx[bi]; curP[1] = sy[bi]; curP[2] = sz[bi];
                float* ap = out + ((size_t)g * MANCH + step) * 3;
                ap[0] = sx[bi]; ap[1] = sy[bi]; ap[2] = sz[bi];
            }
        }
        __syncthreads();
        px = curP[0]; py = curP[1]; pz = curP[2];
    }
}

// ---------------------------------------------------------------------------
// Kernel B: ball query + grouping + 2-layer MLP + max-over-k + sum-over-dt.
// Grid: (8 anchor tiles, 64 groups). Block: 256 threads = 8 warps, each warp
// owns 2 anchors. Warp-per-anchor processing, lane = neighbor slot k.
// ---------------------------------------------------------------------------
__global__ void conv_kernel(const float* __restrict__ xyzs,
                            const float* __restrict__ Wd_g,
                            const float* __restrict__ Wm_g,
                            float* __restrict__ out) {
    extern __shared__ float sm[];
    float* sx  = sm;               // 4096
    float* sy  = sm + NPTS;        // 4096
    float* sz  = sm + 2 * NPTS;    // 4096
    float* sWm = sm + 3 * NPTS;    // 128*64
    float* sWd = sWm + GC1 * GC0;  // 64*4
    int*   sidx = (int*)(sWd + GC0 * 4);  // 8 warps * 32

    int tile = blockIdx.x, g = blockIdx.y;
    int b = g >> 4, f = g & 15;
    int tid = threadIdx.x, warp = tid >> 5, lane = tid & 31;

    for (int i = tid; i < GC1 * GC0; i += CONV_THREADS) sWm[i] = Wm_g[i];
    if (tid < GC0 * 4) sWd[tid] = Wd_g[tid];

    int m0 = tile * 16 + warp * 2;
    float ax[2], ay[2], az[2];
#pragma unroll
    for (int a = 0; a < 2; a++) {
        const float* ap = out + ((size_t)g * MANCH + m0 + a) * 3;
        ax[a] = ap[0]; ay[a] = ap[1]; az[a] = ap[2];
    }

    float acc[2][4];
#pragma unroll
    for (int a = 0; a < 2; a++)
#pragma unroll
        for (int j = 0; j < 4; j++) acc[a][j] = 0.0f;

    int* ib = sidx + warp * KNN;

    for (int dt = -1; dt <= 1; dt++) {
        int t = 2 * f + dt;
        t = t < 0 ? 0 : (t > 31 ? 31 : t);
        const float* frame = xyzs + ((size_t)(b * 32 + t)) * NPTS * 3;
        __syncthreads();  // protect previous dt's SMEM reads before overwrite
        for (int i = tid; i < NPTS; i += CONV_THREADS) {
            sx[i] = frame[3 * i + 0];
            sy[i] = frame[3 * i + 1];
            sz[i] = frame[3 * i + 2];
        }
        __syncthreads();
        float dtf = (float)dt;

#pragma unroll
        for (int a = 0; a < 2; a++) {
            // ---- ball query: first KNN indices with d2 < R^2, ascending order
            int count = 0;
            for (int base = 0; base < NPTS && count < KNN; base += 32) {
                int i = base + lane;
                float d2 = dist2_precise(ax[a], ay[a], az[a], sx[i], sy[i], sz[i]);
                bool within = d2 < RR2;
                unsigned msk = __ballot_sync(0xffffffffu, within);
                int pos = count + __popc(msk & ((1u << lane) - 1u));
                if (within && pos < KNN) ib[pos] = i;
                count += __popc(msk);
            }
            __syncwarp();
            int myIdx = 0;  // no valid neighbor -> index 0 (reference semantics)
            if (count > 0) myIdx = ib[lane < count ? lane : 0];

            float dx = sx[myIdx] - ax[a];
            float dy = sy[myIdx] - ay[a];
            float dz = sz[myIdx] - az[a];

            // ---- layer 1: h1 = relu(Wd @ [dx,dy,dz,dt]), 64 outputs per lane
            float h1[GC0];
#pragma unroll
            for (int i = 0; i < GC0; i++) {
                float4 w = ((const float4*)sWd)[i];
                float v = fmaf(w.x, dx, fmaf(w.y, dy, fmaf(w.z, dz, w.w * dtf)));
                h1[i] = fmaxf(v, 0.0f);
            }

            // ---- layer 2 + max over k (warp lanes) + accumulate over dt
#pragma unroll
            for (int j = 0; j < 4; j++) {
                for (int o32 = 0; o32 < 32; o32++) {
                    int o = j * 32 + o32;
                    const float4* wr = (const float4*)(sWm + o * GC0);
                    float s0 = 0.f, s1 = 0.f, s2 = 0.f, s3 = 0.f;
#pragma unroll
                    for (int i4 = 0; i4 < 16; i4 += 4) {
                        float4 w0 = wr[i4 + 0];
                        float4 w1 = wr[i4 + 1];
                        float4 w2 = wr[i4 + 2];
                        float4 w3 = wr[i4 + 3];
                        s0 = fmaf(w0.x, h1[4*i4 + 0],  fmaf(w0.y, h1[4*i4 + 1],
                             fmaf(w0.z, h1[4*i4 + 2],  fmaf(w0.w, h1[4*i4 + 3],  s0))));
                        s1 = fmaf(w1.x, h1[4*i4 + 4],  fmaf(w1.y, h1[4*i4 + 5],
                             fmaf(w1.z, h1[4*i4 + 6],  fmaf(w1.w, h1[4*i4 + 7],  s1))));
                        s2 = fmaf(w2.x, h1[4*i4 + 8],  fmaf(w2.y, h1[4*i4 + 9],
                             fmaf(w2.z, h1[4*i4 + 10], fmaf(w2.w, h1[4*i4 + 11], s2))));
                        s3 = fmaf(w3.x, h1[4*i4 + 12], fmaf(w3.y, h1[4*i4 + 13],
                             fmaf(w3.z, h1[4*i4 + 14], fmaf(w3.w, h1[4*i4 + 15], s3))));
                    }
                    float s = fmaxf((s0 + s1) + (s2 + s3), 0.0f);
#pragma unroll
                    for (int off = 16; off; off >>= 1)
                        s = fmaxf(s, __shfl_xor_sync(0xffffffffu, s, off));
                    if (lane == o32) acc[a][j] += s;
                }
            }
        }
    }

    // ---- write new_features: out[b,f,o,m] after the new_xyzs block
    float* feat = out + (size_t)GTOT * MANCH * 3;
#pragma unroll
    for (int a = 0; a < 2; a++) {
        int m = m0 + a;
#pragma unroll
        for (int j = 0; j < 4; j++) {
            int o = j * 32 + lane;
            feat[((size_t)g * GC1 + o) * MANCH + m] = acc[a][j];
        }
    }
}

extern "C" void kernel_launch(void* const* d_in, const int* in_sizes, int n_in,
                              void* d_out, int out_size) {
    const float* xyzs = (const float*)d_in[0];
    const float* Wd   = (const float*)d_in[1];
    const float* Wm   = (const float*)d_in[2];
    float* out = (float*)d_out;

    size_t smA = (size_t)3 * NPTS * sizeof(float);                       // 49152
    size_t smB = ((size_t)3 * NPTS + GC1 * GC0 + GC0 * 4) * sizeof(float)
               + 8 * KNN * sizeof(int);                                  // 83968

    cudaFuncSetAttribute(fps_kernel,  cudaFuncAttributeMaxDynamicSharedMemorySize, (int)smA);
    cudaFuncSetAttribute(conv_kernel, cudaFuncAttributeMaxDynamicSharedMemorySize, (int)smB);

    fps_kernel<<<GTOT, FPS_THREADS, smA>>>(xyzs, out);
    conv_kernel<<<dim3(8, GTOT), CONV_THREADS, smB>>>(xyzs, Wd, Wm, out);
}

// round 3
// speedup vs baseline: 1.0078x; 1.0078x over previous
#include <cuda_runtime.h>
#include <cstdint>
#include <cstddef>

#define NPTS   4096
#define MANCH  128
#define GC0    64
#define GC1    128
#define KNN    32
#define RR2    0.0225f
#define GTOT   64
#define FPS_THREADS 512
#define CONV_THREADS 256

// Exact (non-FMA-contracted) squared distance, matching the reference's
// evaluation so discrete decisions (argmax / radius threshold) agree exactly.
__device__ __forceinline__ float dist2_precise(float ax, float ay, float az,
                                               float bx, float by, float bz) {
    float dx = __fsub_rn(ax, bx);
    float dy = __fsub_rn(ay, by);
    float dz = __fsub_rn(az, bz);
    return __fadd_rn(__fadd_rn(__fmul_rn(dx, dx), __fmul_rn(dy, dy)),
                     __fmul_rn(dz, dz));
}

// ---- packed f32x2 helpers (FFMA2: PTX-only on sm_103a) ----
__device__ __forceinline__ unsigned long long pk2(float lo, float hi) {
    unsigned long long r;
    asm("mov.b64 %0, {%1, %2};" : "=l"(r) : "f"(lo), "f"(hi));
    return r;
}
__device__ __forceinline__ void upk2(float& lo, float& hi, unsigned long long v) {
    asm("mov.b64 {%0, %1}, %2;" : "=f"(lo), "=f"(hi) : "l"(v));
}
__device__ __forceinline__ unsigned long long ffma2(unsigned long long a,
                                                    unsigned long long b,
                                                    unsigned long long c) {
    unsigned long long d;
    asm("fma.rn.f32x2 %0, %1, %2, %3;" : "=l"(d) : "l"(a), "l"(b), "l"(c));
    return d;
}
__device__ __forceinline__ unsigned long long fadd2(unsigned long long a,
                                                    unsigned long long b) {
    unsigned long long d;
    asm("add.rn.f32x2 %0, %1, %2;" : "=l"(d) : "l"(a), "l"(b));
    return d;
}

// ---------------------------------------------------------------------------
// Kernel A: furthest point sampling. One block per group (64 blocks).
// Points held in registers (8/lane); smem copy only for pivot lookup/output.
// ---------------------------------------------------------------------------
__global__ void __launch_bounds__(FPS_THREADS) fps_kernel(
    const float* __restrict__ xyzs, float* __restrict__ out) {
    extern __shared__ float sm[];
    float* sx = sm;
    float* sy = sm + NPTS;
    float* sz = sm + 2 * NPTS;
    __shared__ float redV[16];
    __shared__ int   redI[16];
    __shared__ float curP[3];

    int g = blockIdx.x;
    int b = g >> 4, f = g & 15;
    int t = 2 * f;
    const float* frame = xyzs + ((size_t)(b * 32 + t)) * NPTS * 3;
    int tid = threadIdx.x;

    for (int i = tid; i < NPTS; i += FPS_THREADS) {
        sx[i] = frame[3 * i + 0];
        sy[i] = frame[3 * i + 1];
        sz[i] = frame[3 * i + 2];
    }
    __syncthreads();

    float prx[8], pry[8], prz[8], dist[8];
#pragma unroll
    for (int s = 0; s < 8; s++) {
        int i = tid + s * FPS_THREADS;
        prx[s] = sx[i]; pry[s] = sy[i]; prz[s] = sz[i];
        dist[s] = 1e10f;
    }

    if (tid == 0) {
        float* ap = out + (size_t)g * MANCH * 3;
        ap[0] = sx[0]; ap[1] = sy[0]; ap[2] = sz[0];
    }

    float px = sx[0], py = sy[0], pz = sz[0];

    for (int step = 1; step < MANCH; step++) {
        float bv = -1.0f;
        int   bi = NPTS;
#pragma unroll
        for (int s = 0; s < 8; s++) {
            int i = tid + s * FPS_THREADS;
            float d2 = dist2_precise(prx[s], pry[s], prz[s], px, py, pz);
            float dd = fminf(dist[s], d2);
            dist[s] = dd;
            if (dd > bv || (dd == bv && i < bi)) { bv = dd; bi = i; }
        }
#pragma unroll
        for (int off = 16; off; off >>= 1) {
            float ov = __shfl_down_sync(0xffffffffu, bv, off);
            int   oi = __shfl_down_sync(0xffffffffu, bi, off);
            if (ov > bv || (ov == bv && oi < bi)) { bv = ov; bi = oi; }
        }
        if ((tid & 31) == 0) { redV[tid >> 5] = bv; redI[tid >> 5] = bi; }
        __syncthreads();
        if (tid < 32) {
            bv = (tid < 16) ? redV[tid] : -1.0f;
            bi = (tid < 16) ? redI[tid] : NPTS;
#pragma unroll
            for (int off = 8; off; off >>= 1) {
                float ov = __shfl_down_sync(0xffffffffu, bv, off);
                int   oi = __shfl_down_sync(0xffffffffu, bi, off);
                if (ov > bv || (ov == bv && oi < bi)) { bv = ov; bi = oi; }
            }
            if (tid == 0) {
                curP[0] = sx[bi]; curP[1] = sy[bi]; curP[2] = sz[bi];
                float* ap = out + ((size_t)g * MANCH + step) * 3;
                ap[0] = sx[bi]; ap[1] = sy[bi]; ap[2] = sz[bi];
            }
        }
        __syncthreads();
        px = curP[0]; py = curP[1]; pz = curP[2];
    }
}

// ---------------------------------------------------------------------------
// Kernel B: ball query + 2-layer MLP (packed f32x2) + max-over-k + sum-over-dt.
// Grid (8,64), block 256 = 8 warps, warp owns 2 anchors processed JOINTLY so
// every Wm LDS.128 feeds 4 FFMA2 (= 8 fp32 MACs).
// ---------------------------------------------------------------------------
__global__ void __launch_bounds__(CONV_THREADS, 1) conv_kernel(
    const float* __restrict__ xyzs,
    const float* __restrict__ Wd_g,
    const float* __restrict__ Wm_g,
    float* __restrict__ out) {
    extern __shared__ float sm[];
    float* sx  = sm;
    float* sy  = sm + NPTS;
    float* sz  = sm + 2 * NPTS;
    float* sWm = sm + 3 * NPTS;           // 128*64, 16B aligned (offset 48KB)
    float* sWd = sWm + GC1 * GC0;
    int*   sidx = (int*)(sWd + GC0 * 4);  // 8 warps * 32

    int tile = blockIdx.x, g = blockIdx.y;
    int b = g >> 4, f = g & 15;
    int tid = threadIdx.x, warp = tid >> 5, lane = tid & 31;

    for (int i = tid; i < GC1 * GC0; i += CONV_THREADS) sWm[i] = Wm_g[i];
    if (tid < GC0 * 4) sWd[tid] = Wd_g[tid];

    int m0 = tile * 16 + warp * 2;
    const float* ap0 = out + ((size_t)g * MANCH + m0) * 3;
    float ax0 = ap0[0], ay0 = ap0[1], az0 = ap0[2];
    float ax1 = ap0[3], ay1 = ap0[4], az1 = ap0[5];

    float acc[2][4];
#pragma unroll
    for (int a = 0; a < 2; a++)
#pragma unroll
        for (int j = 0; j < 4; j++) acc[a][j] = 0.0f;

    int* ib = sidx + warp * KNN;

    for (int dt = -1; dt <= 1; dt++) {
        int t = 2 * f + dt;
        t = t < 0 ? 0 : (t > 31 ? 31 : t);
        const float* frame = xyzs + ((size_t)(b * 32 + t)) * NPTS * 3;
        __syncthreads();
        for (int i = tid; i < NPTS; i += CONV_THREADS) {
            sx[i] = frame[3 * i + 0];
            sy[i] = frame[3 * i + 1];
            sz[i] = frame[3 * i + 2];
        }
        __syncthreads();
        float dtf = (float)dt;

        // ---- ball query for both anchors (exact semantics as reference)
        float dx0, dy0, dz0, dx1, dy1, dz1;
        {
            int count = 0;
            for (int base = 0; base < NPTS && count < KNN; base += 32) {
                int i = base + lane;
                float d2 = dist2_precise(ax0, ay0, az0, sx[i], sy[i], sz[i]);
                bool within = d2 < RR2;
                unsigned msk = __ballot_sync(0xffffffffu, within);
                int pos = count + __popc(msk & ((1u << lane) - 1u));
                if (within && pos < KNN) ib[pos] = i;
                count += __popc(msk);
            }
            __syncwarp();
            int myIdx = 0;
            if (count > 0) myIdx = ib[lane < count ? lane : 0];
            dx0 = sx[myIdx] - ax0; dy0 = sy[myIdx] - ay0; dz0 = sz[myIdx] - az0;
        }
        {
            int count = 0;
            for (int base = 0; base < NPTS && count < KNN; base += 32) {
                int i = base + lane;
                float d2 = dist2_precise(ax1, ay1, az1, sx[i], sy[i], sz[i]);
                bool within = d2 < RR2;
                unsigned msk = __ballot_sync(0xffffffffu, within);
                int pos = count + __popc(msk & ((1u << lane) - 1u));
                if (within && pos < KNN) ib[pos] = i;
                count += __popc(msk);
            }
            __syncwarp();
            int myIdx = 0;
            if (count > 0) myIdx = ib[lane < count ? lane : 0];
            dx1 = sx[myIdx] - ax1; dy1 = sy[myIdx] - ay1; dz1 = sz[myIdx] - az1;
        }

        // ---- layer 1: h1 = relu(Wd @ [dx,dy,dz,dt]) packed as f32x2 over i
        unsigned long long h1a[GC0 / 2], h1b[GC0 / 2];
#pragma unroll
        for (int q = 0; q < GC0 / 2; q++) {
            float4 w0 = ((const float4*)sWd)[2 * q];
            float4 w1 = ((const float4*)sWd)[2 * q + 1];
            float v0a = fmaf(w0.x, dx0, fmaf(w0.y, dy0, fmaf(w0.z, dz0, w0.w * dtf)));
            float v1a = fmaf(w1.x, dx0, fmaf(w1.y, dy0, fmaf(w1.z, dz0, w1.w * dtf)));
            float v0b = fmaf(w0.x, dx1, fmaf(w0.y, dy1, fmaf(w0.z, dz1, w0.w * dtf)));
            float v1b = fmaf(w1.x, dx1, fmaf(w1.y, dy1, fmaf(w1.z, dz1, w1.w * dtf)));
            h1a[q] = pk2(fmaxf(v0a, 0.0f), fmaxf(v1a, 0.0f));
            h1b[q] = pk2(fmaxf(v0b, 0.0f), fmaxf(v1b, 0.0f));
        }

        // ---- layer 2 (both anchors share each Wm load) + max over k + sum dt
#pragma unroll 2
        for (int o = 0; o < GC1; o++) {
            const ulonglong2* wr = (const ulonglong2*)(sWm + o * GC0);
            unsigned long long sa0 = 0ull, sa1 = 0ull, sb0 = 0ull, sb1 = 0ull;
#pragma unroll
            for (int q = 0; q < 16; q++) {
                ulonglong2 w = wr[q];
                sa0 = ffma2(h1a[2 * q + 0], w.x, sa0);
                sa1 = ffma2(h1a[2 * q + 1], w.y, sa1);
                sb0 = ffma2(h1b[2 * q + 0], w.x, sb0);
                sb1 = ffma2(h1b[2 * q + 1], w.y, sb1);
            }
            unsigned long long ta = fadd2(sa0, sa1);
            unsigned long long tb = fadd2(sb0, sb1);
            float alo, ahi, blo, bhi;
            upk2(alo, ahi, ta);
            upk2(blo, bhi, tb);
            float sA = fmaxf(alo + ahi, 0.0f);
            float sB = fmaxf(blo + bhi, 0.0f);
#pragma unroll
            for (int off = 16; off; off >>= 1) {
                sA = fmaxf(sA, __shfl_xor_sync(0xffffffffu, sA, off));
                sB = fmaxf(sB, __shfl_xor_sync(0xffffffffu, sB, off));
            }
            if (lane == (o & 31)) {
                acc[0][o >> 5] += sA;
                acc[1][o >> 5] += sB;
            }
        }
    }

    // ---- write new_features: out[b,f,o,m] after the new_xyzs block
    float* feat = out + (size_t)GTOT * MANCH * 3;
#pragma unroll
    for (int a = 0; a < 2; a++) {
        int m = m0 + a;
#pragma unroll
        for (int j = 0; j < 4; j++) {
            int o = j * 32 + lane;
            feat[((size_t)g * GC1 + o) * MANCH + m] = acc[a][j];
        }
    }
}

extern "C" void kernel_launch(void* const* d_in, const int* in_sizes, int n_in,
                              void* d_out, int out_size) {
    const float* xyzs = (const float*)d_in[0];
    const float* Wd   = (const float*)d_in[1];
    const float* Wm   = (const float*)d_in[2];
    float* out = (float*)d_out;

    size_t smA = (size_t)3 * NPTS * sizeof(float);
    size_t smB = ((size_t)3 * NPTS + GC1 * GC0 + GC0 * 4) * sizeof(float)
               + 8 * KNN * sizeof(int);

    cudaFuncSetAttribute(fps_kernel,  cudaFuncAttributeMaxDynamicSharedMemorySize, (int)smA);
    cudaFuncSetAttribute(conv_kernel, cudaFuncAttributeMaxDynamicSharedMemorySize, (int)smB);

    fps_kernel<<<GTOT, FPS_THREADS, smA>>>(xyzs, out);
    conv_kernel<<<dim3(8, GTOT), CONV_THREADS, smB>>>(xyzs, Wd, Wm, out);
}

// round 4
// speedup vs baseline: 1.1584x; 1.1494x over previous
#include <cuda_runtime.h>
#include <cstdint>
#include <cstddef>

#define NPTS   4096
#define MANCH  128
#define GC0    64
#define GC1    128
#define KNN    32
#define RR2    0.0225f
#define GTOT   64
#define FPS_THREADS 512
#define CONV_THREADS 256

// Exact (non-FMA-contracted) squared distance, matching the reference's
// evaluation so discrete decisions (argmax / radius threshold) agree exactly.
__device__ __forceinline__ float dist2_precise(float ax, float ay, float az,
                                               float bx, float by, float bz) {
    float dx = __fsub_rn(ax, bx);
    float dy = __fsub_rn(ay, by);
    float dz = __fsub_rn(az, bz);
    return __fadd_rn(__fadd_rn(__fmul_rn(dx, dx), __fmul_rn(dy, dy)),
                     __fmul_rn(dz, dz));
}

// ---- packed f32x2 helpers ----
__device__ __forceinline__ unsigned long long pk2(float lo, float hi) {
    unsigned long long r;
    asm("mov.b64 %0, {%1, %2};" : "=l"(r) : "f"(lo), "f"(hi));
    return r;
}
__device__ __forceinline__ void upk2(float& lo, float& hi, unsigned long long v) {
    asm("mov.b64 {%0, %1}, %2;" : "=f"(lo), "=f"(hi) : "l"(v));
}
__device__ __forceinline__ unsigned long long ffma2(unsigned long long a,
                                                    unsigned long long b,
                                                    unsigned long long c) {
    unsigned long long d;
    asm("fma.rn.f32x2 %0, %1, %2, %3;" : "=l"(d) : "l"(a), "l"(b), "l"(c));
    return d;
}
__device__ __forceinline__ unsigned long long fadd2(unsigned long long a,
                                                    unsigned long long b) {
    unsigned long long d;
    asm("add.rn.f32x2 %0, %1, %2;" : "=l"(d) : "l"(a), "l"(b));
    return d;
}
// warp max of a non-negative float via integer redux (bit-monotonic for >=0)
__device__ __forceinline__ float warp_max_nonneg(float v) {
    unsigned u = __float_as_uint(v), r;
    asm("redux.sync.max.u32 %0, %1, 0xffffffff;" : "=r"(r) : "r"(u));
    return __uint_as_float(r);
}

// ---------------------------------------------------------------------------
// Kernel A: furthest point sampling. One block per group (64 blocks).
// ---------------------------------------------------------------------------
__global__ void __launch_bounds__(FPS_THREADS) fps_kernel(
    const float* __restrict__ xyzs, float* __restrict__ out) {
    extern __shared__ float sm[];
    float* sx = sm;
    float* sy = sm + NPTS;
    float* sz = sm + 2 * NPTS;
    __shared__ float redV[16];
    __shared__ int   redI[16];
    __shared__ float curP[3];

    int g = blockIdx.x;
    int b = g >> 4, f = g & 15;
    int t = 2 * f;
    const float* frame = xyzs + ((size_t)(b * 32 + t)) * NPTS * 3;
    int tid = threadIdx.x;

    for (int i = tid; i < NPTS; i += FPS_THREADS) {
        sx[i] = frame[3 * i + 0];
        sy[i] = frame[3 * i + 1];
        sz[i] = frame[3 * i + 2];
    }
    __syncthreads();

    float prx[8], pry[8], prz[8], dist[8];
#pragma unroll
    for (int s = 0; s < 8; s++) {
        int i = tid + s * FPS_THREADS;
        prx[s] = sx[i]; pry[s] = sy[i]; prz[s] = sz[i];
        dist[s] = 1e10f;
    }

    if (tid == 0) {
        float* ap = out + (size_t)g * MANCH * 3;
        ap[0] = sx[0]; ap[1] = sy[0]; ap[2] = sz[0];
    }

    float px = sx[0], py = sy[0], pz = sz[0];

    for (int step = 1; step < MANCH; step++) {
        float bv = -1.0f;
        int   bi = NPTS;
#pragma unroll
        for (int s = 0; s < 8; s++) {
            int i = tid + s * FPS_THREADS;
            float d2 = dist2_precise(prx[s], pry[s], prz[s], px, py, pz);
            float dd = fminf(dist[s], d2);
            dist[s] = dd;
            if (dd > bv || (dd == bv && i < bi)) { bv = dd; bi = i; }
        }
#pragma unroll
        for (int off = 16; off; off >>= 1) {
            float ov = __shfl_down_sync(0xffffffffu, bv, off);
            int   oi = __shfl_down_sync(0xffffffffu, bi, off);
            if (ov > bv || (ov == bv && oi < bi)) { bv = ov; bi = oi; }
        }
        if ((tid & 31) == 0) { redV[tid >> 5] = bv; redI[tid >> 5] = bi; }
        __syncthreads();
        if (tid < 32) {
            bv = (tid < 16) ? redV[tid] : -1.0f;
            bi = (tid < 16) ? redI[tid] : NPTS;
#pragma unroll
            for (int off = 8; off; off >>= 1) {
                float ov = __shfl_down_sync(0xffffffffu, bv, off);
                int   oi = __shfl_down_sync(0xffffffffu, bi, off);
                if (ov > bv || (ov == bv && oi < bi)) { bv = ov; bi = oi; }
            }
            if (tid == 0) {
                curP[0] = sx[bi]; curP[1] = sy[bi]; curP[2] = sz[bi];
                float* ap = out + ((size_t)g * MANCH + step) * 3;
                ap[0] = sx[bi]; ap[1] = sy[bi]; ap[2] = sz[bi];
            }
        }
        __syncthreads();
        px = curP[0]; py = curP[1]; pz = curP[2];
    }
}

// ---------------------------------------------------------------------------
// Kernel B: ball query + 2-layer MLP + max-over-k + sum-over-dt.
// Grid (8,64), block 256 = 8 warps. Warp owns 2 anchors, processed
// SEQUENTIALLY (one h1 array live -> ~110 regs -> 2 blocks/SM).
// ---------------------------------------------------------------------------
__global__ void __launch_bounds__(CONV_THREADS, 2) conv_kernel(
    const float* __restrict__ xyzs,
    const float* __restrict__ Wd_g,
    const float* __restrict__ Wm_g,
    float* __restrict__ out) {
    extern __shared__ float sm[];
    float* sx  = sm;
    float* sy  = sm + NPTS;
    float* sz  = sm + 2 * NPTS;
    float* sWm = sm + 3 * NPTS;           // 128*64, 16B aligned
    float* sWd = sWm + GC1 * GC0;
    int*   sidx = (int*)(sWd + GC0 * 4);  // 8 warps * 32

    int tile = blockIdx.x, g = blockIdx.y;
    int b = g >> 4, f = g & 15;
    int tid = threadIdx.x, warp = tid >> 5, lane = tid & 31;

    for (int i = tid; i < GC1 * GC0; i += CONV_THREADS) sWm[i] = Wm_g[i];
    if (tid < GC0 * 4) sWd[tid] = Wd_g[tid];

    int m0 = tile * 16 + warp * 2;
    const float* ap0 = out + ((size_t)g * MANCH + m0) * 3;
    float anc[2][3];
    anc[0][0] = ap0[0]; anc[0][1] = ap0[1]; anc[0][2] = ap0[2];
    anc[1][0] = ap0[3]; anc[1][1] = ap0[4]; anc[1][2] = ap0[5];

    float acc[2][4];
#pragma unroll
    for (int a = 0; a < 2; a++)
#pragma unroll
        for (int j = 0; j < 4; j++) acc[a][j] = 0.0f;

    int* ib = sidx + warp * KNN;

    for (int dt = -1; dt <= 1; dt++) {
        int t = 2 * f + dt;
        t = t < 0 ? 0 : (t > 31 ? 31 : t);
        const float* frame = xyzs + ((size_t)(b * 32 + t)) * NPTS * 3;
        __syncthreads();  // previous dt's smem reads complete before overwrite
        for (int i = tid; i < NPTS; i += CONV_THREADS) {
            sx[i] = frame[3 * i + 0];
            sy[i] = frame[3 * i + 1];
            sz[i] = frame[3 * i + 2];
        }
        __syncthreads();
        float dtf = (float)dt;

        for (int a = 0; a < 2; a++) {
            float ax = anc[a][0], ay = anc[a][1], az = anc[a][2];

            // ---- ball query: first KNN indices with d2 < R^2, ascending
            int count = 0;
            for (int base = 0; base < NPTS && count < KNN; base += 32) {
                int i = base + lane;
                float d2 = dist2_precise(ax, ay, az, sx[i], sy[i], sz[i]);
                bool within = d2 < RR2;
                unsigned msk = __ballot_sync(0xffffffffu, within);
                int pos = count + __popc(msk & ((1u << lane) - 1u));
                if (within && pos < KNN) ib[pos] = i;
                count += __popc(msk);
            }
            __syncwarp();
            int myIdx = 0;  // no valid neighbor -> index 0 (reference semantics)
            if (count > 0) myIdx = ib[lane < count ? lane : 0];

            float dx = sx[myIdx] - ax;
            float dy = sy[myIdx] - ay;
            float dz = sz[myIdx] - az;

            // ---- layer 1: h1 = relu(Wd @ [dx,dy,dz,dt]), packed over i-pairs
            unsigned long long h1[GC0 / 2];
#pragma unroll
            for (int q = 0; q < GC0 / 2; q++) {
                float4 w0 = ((const float4*)sWd)[2 * q];
                float4 w1 = ((const float4*)sWd)[2 * q + 1];
                float v0 = fmaf(w0.x, dx, fmaf(w0.y, dy, fmaf(w0.z, dz, w0.w * dtf)));
                float v1 = fmaf(w1.x, dx, fmaf(w1.y, dy, fmaf(w1.z, dz, w1.w * dtf)));
                h1[q] = pk2(fmaxf(v0, 0.0f), fmaxf(v1, 0.0f));
            }

            // ---- layer 2 + max over k (redux) + accumulate over dt
#pragma unroll 2
            for (int o = 0; o < GC1; o++) {
                const ulonglong2* wr = (const ulonglong2*)(sWm + o * GC0);
                unsigned long long s0 = 0ull, s1 = 0ull, s2 = 0ull, s3 = 0ull;
#pragma unroll
                for (int q = 0; q < 16; q += 2) {
                    ulonglong2 wA = wr[q];
                    ulonglong2 wB = wr[q + 1];
                    s0 = ffma2(h1[2 * q + 0], wA.x, s0);
                    s1 = ffma2(h1[2 * q + 1], wA.y, s1);
                    s2 = ffma2(h1[2 * q + 2], wB.x, s2);
                    s3 = ffma2(h1[2 * q + 3], wB.y, s3);
                }
                unsigned long long tt = fadd2(fadd2(s0, s2), fadd2(s1, s3));
                float lo, hi;
                upk2(lo, hi, tt);
                float s = fmaxf(lo + hi, 0.0f);
                s = warp_max_nonneg(s);
                if (lane == (o & 31)) acc[a][o >> 5] += s;
            }
        }
    }

    // ---- write new_features: out[b,f,o,m] after the new_xyzs block
    float* feat = out + (size_t)GTOT * MANCH * 3;
#pragma unroll
    for (int a = 0; a < 2; a++) {
        int m = m0 + a;
#pragma unroll
        for (int j = 0; j < 4; j++) {
            int o = j * 32 + lane;
            feat[((size_t)g * GC1 + o) * MANCH + m] = acc[a][j];
        }
    }
}

extern "C" void kernel_launch(void* const* d_in, const int* in_sizes, int n_in,
                              void* d_out, int out_size) {
    const float* xyzs = (const float*)d_in[0];
    const float* Wd   = (const float*)d_in[1];
    const float* Wm   = (const float*)d_in[2];
    float* out = (float*)d_out;

    size_t smA = (size_t)3 * NPTS * sizeof(float);
    size_t smB = ((size_t)3 * NPTS + GC1 * GC0 + GC0 * 4) * sizeof(float)
               + 8 * KNN * sizeof(int);

    cudaFuncSetAttribute(fps_kernel,  cudaFuncAttributeMaxDynamicSharedMemorySize, (int)smA);
    cudaFuncSetAttribute(conv_kernel, cudaFuncAttributeMaxDynamicSharedMemorySize, (int)smB);

    fps_kernel<<<GTOT, FPS_THREADS, smA>>>(xyzs, out);
    conv_kernel<<<dim3(8, GTOT), CONV_THREADS, smB>>>(xyzs, Wd, Wm, out);
}